// round 5
// baseline (speedup 1.0000x reference)
#include <cuda_runtime.h>

typedef unsigned long long u64;

// ---------------------------------------------------------------------------
// Packed fp32x2 helpers (sm_100-family FFMA2 path: 2x fp32 FMA throughput)
// ---------------------------------------------------------------------------
static __device__ __forceinline__ u64 pk2(float lo, float hi) {
    u64 r;
    asm("mov.b64 %0, {%1, %2};" : "=l"(r) : "f"(lo), "f"(hi));
    return r;
}
static __device__ __forceinline__ void upk2(u64 v, float& lo, float& hi) {
    asm("mov.b64 {%0, %1}, %2;" : "=f"(lo), "=f"(hi) : "l"(v));
}
static __device__ __forceinline__ u64 ffma2(u64 a, u64 b, u64 c) {
    u64 d;
    asm("fma.rn.f32x2 %0, %1, %2, %3;" : "=l"(d) : "l"(a), "l"(b), "l"(c));
    return d;
}
static __device__ __forceinline__ u64 relu2(u64 v) {
    float lo, hi;
    upk2(v, lo, hi);
    return pk2(fmaxf(lo, 0.0f), fmaxf(hi, 0.0f));
}
static __device__ __forceinline__ float sigf(float z) {
    return __fdividef(1.0f, 1.0f + __expf(-z));
}

// ---------------------------------------------------------------------------
// Scalar compile-time constants (scalars at namespace scope are fine in
// device code; ARRAYS are not -> the shape arrays live inside the kernel).
// ---------------------------------------------------------------------------
constexpr int NW = 1476;   // total packed weight elements
constexpr int NB = 109;    // total packed bias elements

constexpr int THREADS = 128;
constexpr int ROWS_PER_BLOCK = 4 * THREADS;   // 4 rows per thread (2 packed pairs)

struct Params {
    const float* W[10];
    const float* b[10];
};

// One fully-unrolled layer over two packed row-pairs.
// in0/in1: IN packed activations for pair0/pair1; out0/out1: OUT packed outputs.
// Each smem weight LDS.64 ({w,w}) feeds TWO ffma2 (4 MACs) -> LDS:FFMA2 = 1:2.
template <int IN, int OUT, bool RELU>
static __device__ __forceinline__ void layer(
    const float2* __restrict__ sw, const float2* __restrict__ sb,
    const u64* in0, const u64* in1, u64* out0, u64* out1)
{
#pragma unroll
    for (int j = 0; j < OUT; ++j) {
        u64 bb = *reinterpret_cast<const u64*>(sb + j);
        out0[j] = bb;
        out1[j] = bb;
    }
#pragma unroll
    for (int k = 0; k < IN; ++k) {
        u64 x0 = in0[k];
        u64 x1 = in1[k];
#pragma unroll
        for (int j = 0; j < OUT; ++j) {
            u64 w = *reinterpret_cast<const u64*>(sw + k * OUT + j);
            out0[j] = ffma2(x0, w, out0[j]);
            out1[j] = ffma2(x1, w, out1[j]);
        }
    }
    if (RELU) {
#pragma unroll
        for (int j = 0; j < OUT; ++j) {
            out0[j] = relu2(out0[j]);
            out1[j] = relu2(out1[j]);
        }
    }
}

__global__ void __launch_bounds__(THREADS)
mlp_fused_kernel(const float* __restrict__ x, float* __restrict__ out,
                 Params p, int rows)
{
    // Function-local constexpr arrays: legal in device code, fully folded.
    constexpr int DIMS[11] = {8, 20, 18, 16, 14, 12, 10, 8, 6, 4, 1};
    constexpr int WOFF[10] = {0, 160, 520, 808, 1032, 1200, 1320, 1400, 1448, 1472};
    constexpr int BOFF[10] = {0, 20, 38, 54, 68, 80, 90, 98, 104, 108};

    __shared__ float2 sW[NW];
    __shared__ float2 sB[NB];

    const int tid = threadIdx.x;

    // --- Stage packed {w,w} weights + biases into shared memory -----------
#pragma unroll
    for (int l = 0; l < 10; ++l) {
        const int n = DIMS[l] * DIMS[l + 1];
        for (int i = tid; i < n; i += THREADS) {
            float w = p.W[l][i];
            sW[WOFF[l] + i] = make_float2(w, w);
        }
        if (tid < DIMS[l + 1]) {
            float bb = p.b[l][tid];
            sB[BOFF[l] + tid] = make_float2(bb, bb);
        }
    }
    __syncthreads();

    // --- Row assignment: 4 rows per thread, coalesced --------------------
    const long base = (long)blockIdx.x * ROWS_PER_BLOCK;
    const int r0 = (int)base + tid;
    const int r1 = r0 + THREADS;
    const int r2 = r0 + 2 * THREADS;
    const int r3 = r0 + 3 * THREADS;
    const bool g0 = r0 < rows, g1 = r1 < rows, g2 = r2 < rows, g3 = r3 < rows;

    const float4* __restrict__ X = (const float4*)x;
    const float4 z4 = make_float4(0.f, 0.f, 0.f, 0.f);
    float4 v0a = g0 ? X[2 * r0] : z4, v0b = g0 ? X[2 * r0 + 1] : z4;
    float4 v1a = g1 ? X[2 * r1] : z4, v1b = g1 ? X[2 * r1 + 1] : z4;
    float4 v2a = g2 ? X[2 * r2] : z4, v2b = g2 ? X[2 * r2 + 1] : z4;
    float4 v3a = g3 ? X[2 * r3] : z4, v3b = g3 ? X[2 * r3 + 1] : z4;

    // Two ping-pong register banks per pair (max layer width = 20)
    u64 A0[20], A1[20], B0[20], B1[20];

    // pair0 = rows (r0, r1); pair1 = rows (r2, r3)
    A0[0] = pk2(v0a.x, v1a.x);  A1[0] = pk2(v2a.x, v3a.x);
    A0[1] = pk2(v0a.y, v1a.y);  A1[1] = pk2(v2a.y, v3a.y);
    A0[2] = pk2(v0a.z, v1a.z);  A1[2] = pk2(v2a.z, v3a.z);
    A0[3] = pk2(v0a.w, v1a.w);  A1[3] = pk2(v2a.w, v3a.w);
    A0[4] = pk2(v0b.x, v1b.x);  A1[4] = pk2(v2b.x, v3b.x);
    A0[5] = pk2(v0b.y, v1b.y);  A1[5] = pk2(v2b.y, v3b.y);
    A0[6] = pk2(v0b.z, v1b.z);  A1[6] = pk2(v2b.z, v3b.z);
    A0[7] = pk2(v0b.w, v1b.w);  A1[7] = pk2(v2b.w, v3b.w);

    // --- 10 fused layers (ping-pong A <-> B) ------------------------------
    layer< 8, 20, true >(sW + WOFF[0], sB + BOFF[0], A0, A1, B0, B1);
    layer<20, 18, true >(sW + WOFF[1], sB + BOFF[1], B0, B1, A0, A1);
    layer<18, 16, true >(sW + WOFF[2], sB + BOFF[2], A0, A1, B0, B1);
    layer<16, 14, true >(sW + WOFF[3], sB + BOFF[3], B0, B1, A0, A1);
    layer<14, 12, true >(sW + WOFF[4], sB + BOFF[4], A0, A1, B0, B1);
    layer<12, 10, true >(sW + WOFF[5], sB + BOFF[5], B0, B1, A0, A1);
    layer<10,  8, true >(sW + WOFF[6], sB + BOFF[6], A0, A1, B0, B1);
    layer< 8,  6, true >(sW + WOFF[7], sB + BOFF[7], B0, B1, A0, A1);
    layer< 6,  4, true >(sW + WOFF[8], sB + BOFF[8], A0, A1, B0, B1);
    layer< 4,  1, false>(sW + WOFF[9], sB + BOFF[9], B0, B1, A0, A1);

    // --- Sigmoid + store --------------------------------------------------
    float za, zb;
    upk2(A0[0], za, zb);
    if (g0) out[r0] = sigf(za);
    if (g1) out[r1] = sigf(zb);
    upk2(A1[0], za, zb);
    if (g2) out[r2] = sigf(za);
    if (g3) out[r3] = sigf(zb);
}

extern "C" void kernel_launch(void* const* d_in, const int* in_sizes, int n_in,
                              void* d_out, int out_size)
{
    const float* x = (const float*)d_in[0];
    Params p;
    for (int i = 0; i < 10; ++i) {
        p.W[i] = (const float*)d_in[1 + 2 * i];
        p.b[i] = (const float*)d_in[2 + 2 * i];
    }
    const int rows = in_sizes[0] / 8;   // x is [rows, 8] fp32
    const int grid = (rows + ROWS_PER_BLOCK - 1) / ROWS_PER_BLOCK;
    mlp_fused_kernel<<<grid, THREADS>>>(x, (float*)d_out, p, rows);
}

// round 6
// speedup vs baseline: 1.0203x; 1.0203x over previous
#include <cuda_runtime.h>

typedef unsigned long long u64;

// ---------------------------------------------------------------------------
// Packed fp32x2 helpers (sm_100-family FFMA2: 2x fp32 FMA throughput)
// ---------------------------------------------------------------------------
union F2 {
    u64    u;
    float2 f;
};

static __device__ __forceinline__ u64 pk2(float lo, float hi) {
    F2 r;
    r.f = make_float2(lo, hi);
    return r.u;
}
static __device__ __forceinline__ u64 ffma2(u64 a, u64 b, u64 c) {
    u64 d;
    asm("fma.rn.f32x2 %0, %1, %2, %3;" : "=l"(d) : "l"(a), "l"(b), "l"(c));
    return d;
}
static __device__ __forceinline__ float sigf(float z) {
    return __fdividef(1.0f, 1.0f + __expf(-z));
}

// ---------------------------------------------------------------------------
// Compile-time scalar constants
// ---------------------------------------------------------------------------
constexpr int NW4 = 738;   // packed float4 weight elements ({wj,wj,wj+1,wj+1})
constexpr int NB  = 109;   // packed {b,b} bias elements

constexpr int THREADS = 128;
constexpr int ROWS_PER_BLOCK = 4 * THREADS;   // 4 rows/thread (2 packed row-pairs)

struct Params {
    const float* W[10];
    const float* b[10];
};

// ---------------------------------------------------------------------------
// One fully-unrolled layer (even OUT) over two packed row-pairs.
// One LDS.128 = {wj,wj,wj+1,wj+1} feeds FOUR ffma2  ->  LDS:FFMA2 = 1:4.
// ---------------------------------------------------------------------------
template <int IN, int OUT, bool RELU>
static __device__ __forceinline__ void layer(
    const ulonglong2* __restrict__ sw, const float2* __restrict__ sb,
    const F2* in0, const F2* in1, F2* out0, F2* out1)
{
    static_assert(OUT % 2 == 0, "even OUT only");
#pragma unroll
    for (int j = 0; j < OUT; ++j) {
        u64 bb = *reinterpret_cast<const u64*>(sb + j);   // one LDS.64
        out0[j].u = bb;
        out1[j].u = bb;
    }
#pragma unroll
    for (int k = 0; k < IN; ++k) {
        const u64 x0 = in0[k].u;
        const u64 x1 = in1[k].u;
#pragma unroll
        for (int j2 = 0; j2 < OUT / 2; ++j2) {
            const ulonglong2 w = sw[k * (OUT / 2) + j2];  // one LDS.128
            out0[2 * j2    ].u = ffma2(x0, w.x, out0[2 * j2    ].u);
            out1[2 * j2    ].u = ffma2(x1, w.x, out1[2 * j2    ].u);
            out0[2 * j2 + 1].u = ffma2(x0, w.y, out0[2 * j2 + 1].u);
            out1[2 * j2 + 1].u = ffma2(x1, w.y, out1[2 * j2 + 1].u);
        }
    }
    if (RELU) {
#pragma unroll
        for (int j = 0; j < OUT; ++j) {   // in-place FMNMX on pair halves, no movs
            out0[j].f.x = fmaxf(out0[j].f.x, 0.0f);
            out0[j].f.y = fmaxf(out0[j].f.y, 0.0f);
            out1[j].f.x = fmaxf(out1[j].f.x, 0.0f);
            out1[j].f.y = fmaxf(out1[j].f.y, 0.0f);
        }
    }
}

__global__ void __launch_bounds__(THREADS, 2)
mlp_fused_kernel(const float* __restrict__ x, float* __restrict__ out,
                 Params p, int rows)
{
    // Function-local constexpr arrays (legal in device code, fully folded).
    constexpr int DIMS[11]  = {8, 20, 18, 16, 14, 12, 10, 8, 6, 4, 1};
    constexpr int WOFF4[10] = {0, 80, 260, 404, 516, 600, 660, 700, 724, 736};
    constexpr int BOFF[10]  = {0, 20, 38, 54, 68, 80, 90, 98, 104, 108};

    __shared__ ulonglong2 sW[NW4];   // {wj,wj,wj+1,wj+1} per element (16B aligned)
    __shared__ float2     sB[NB];    // {b,b}

    const int tid = threadIdx.x;

    // --- Stage packed weights + biases into shared memory -----------------
#pragma unroll
    for (int l = 0; l < 9; ++l) {
        const int OUT = DIMS[l + 1];
        const int n4  = DIMS[l] * OUT / 2;
        for (int i = tid; i < n4; i += THREADS) {
            const int k  = i / (OUT / 2);
            const int j2 = i % (OUT / 2);
            const float w0 = p.W[l][k * OUT + 2 * j2];
            const float w1 = p.W[l][k * OUT + 2 * j2 + 1];
            F2 a, b; a.f = make_float2(w0, w0); b.f = make_float2(w1, w1);
            sW[WOFF4[l] + i] = make_ulonglong2(a.u, b.u);
        }
        if (tid < OUT) {
            const float bb = p.b[l][tid];
            sB[BOFF[l] + tid] = make_float2(bb, bb);
        }
    }
    // Last layer (IN=4, OUT=1): pack pairs of k: {w_k,w_k,w_{k+1},w_{k+1}}
    if (tid < 2) {
        const float w0 = p.W[9][2 * tid];
        const float w1 = p.W[9][2 * tid + 1];
        F2 a, b; a.f = make_float2(w0, w0); b.f = make_float2(w1, w1);
        sW[WOFF4[9] + tid] = make_ulonglong2(a.u, b.u);
    }
    if (tid == 0) {
        const float bb = p.b[9][0];
        sB[BOFF[9]] = make_float2(bb, bb);
    }
    __syncthreads();

    // --- Row assignment: 4 rows per thread, coalesced ---------------------
    const long base = (long)blockIdx.x * ROWS_PER_BLOCK;
    const int r0 = (int)base + tid;
    const int r1 = r0 + THREADS;
    const int r2 = r0 + 2 * THREADS;
    const int r3 = r0 + 3 * THREADS;
    const bool g0 = r0 < rows, g1 = r1 < rows, g2 = r2 < rows, g3 = r3 < rows;

    const float4* __restrict__ X = (const float4*)x;
    const float4 z4 = make_float4(0.f, 0.f, 0.f, 0.f);
    float4 v0a = g0 ? X[2 * r0] : z4, v0b = g0 ? X[2 * r0 + 1] : z4;
    float4 v1a = g1 ? X[2 * r1] : z4, v1b = g1 ? X[2 * r1 + 1] : z4;
    float4 v2a = g2 ? X[2 * r2] : z4, v2b = g2 ? X[2 * r2 + 1] : z4;
    float4 v3a = g3 ? X[2 * r3] : z4, v3b = g3 ? X[2 * r3 + 1] : z4;

    // Two ping-pong register banks per row-pair (max layer width = 20)
    F2 A0[20], A1[20], B0[20], B1[20];

    // pair0 = rows (r0, r1); pair1 = rows (r2, r3)
    A0[0].u = pk2(v0a.x, v1a.x);  A1[0].u = pk2(v2a.x, v3a.x);
    A0[1].u = pk2(v0a.y, v1a.y);  A1[1].u = pk2(v2a.y, v3a.y);
    A0[2].u = pk2(v0a.z, v1a.z);  A1[2].u = pk2(v2a.z, v3a.z);
    A0[3].u = pk2(v0a.w, v1a.w);  A1[3].u = pk2(v2a.w, v3a.w);
    A0[4].u = pk2(v0b.x, v1b.x);  A1[4].u = pk2(v2b.x, v3b.x);
    A0[5].u = pk2(v0b.y, v1b.y);  A1[5].u = pk2(v2b.y, v3b.y);
    A0[6].u = pk2(v0b.z, v1b.z);  A1[6].u = pk2(v2b.z, v3b.z);
    A0[7].u = pk2(v0b.w, v1b.w);  A1[7].u = pk2(v2b.w, v3b.w);

    // --- 9 even-OUT fused layers (ping-pong A <-> B) ----------------------
    layer< 8, 20, true>(sW + WOFF4[0], sB + BOFF[0], A0, A1, B0, B1);
    layer<20, 18, true>(sW + WOFF4[1], sB + BOFF[1], B0, B1, A0, A1);
    layer<18, 16, true>(sW + WOFF4[2], sB + BOFF[2], A0, A1, B0, B1);
    layer<16, 14, true>(sW + WOFF4[3], sB + BOFF[3], B0, B1, A0, A1);
    layer<14, 12, true>(sW + WOFF4[4], sB + BOFF[4], A0, A1, B0, B1);
    layer<12, 10, true>(sW + WOFF4[5], sB + BOFF[5], B0, B1, A0, A1);
    layer<10,  8, true>(sW + WOFF4[6], sB + BOFF[6], A0, A1, B0, B1);
    layer< 8,  6, true>(sW + WOFF4[7], sB + BOFF[7], B0, B1, A0, A1);
    layer< 6,  4, true>(sW + WOFF4[8], sB + BOFF[8], A0, A1, B0, B1);

    // --- Last layer: IN=4, OUT=1, k packed in pairs -----------------------
    u64 acc0, acc1;
    {
        const u64 bb = *reinterpret_cast<const u64*>(sB + BOFF[9]);
        acc0 = bb;  acc1 = bb;
        const ulonglong2 wA = (sW + WOFF4[9])[0];   // k=0,1
        const ulonglong2 wB = (sW + WOFF4[9])[1];   // k=2,3
        acc0 = ffma2(B0[0].u, wA.x, acc0);
        acc1 = ffma2(B1[0].u, wA.x, acc1);
        acc0 = ffma2(B0[1].u, wA.y, acc0);
        acc1 = ffma2(B1[1].u, wA.y, acc1);
        acc0 = ffma2(B0[2].u, wB.x, acc0);
        acc1 = ffma2(B1[2].u, wB.x, acc1);
        acc0 = ffma2(B0[3].u, wB.y, acc0);
        acc1 = ffma2(B1[3].u, wB.y, acc1);
    }

    // --- Sigmoid + store --------------------------------------------------
    F2 z0, z1;
    z0.u = acc0;  z1.u = acc1;
    if (g0) out[r0] = sigf(z0.f.x);
    if (g1) out[r1] = sigf(z0.f.y);
    if (g2) out[r2] = sigf(z1.f.x);
    if (g3) out[r3] = sigf(z1.f.y);
}

extern "C" void kernel_launch(void* const* d_in, const int* in_sizes, int n_in,
                              void* d_out, int out_size)
{
    const float* x = (const float*)d_in[0];
    Params p;
    for (int i = 0; i < 10; ++i) {
        p.W[i] = (const float*)d_in[1 + 2 * i];
        p.b[i] = (const float*)d_in[2 + 2 * i];
    }
    const int rows = in_sizes[0] / 8;   // x is [rows, 8] fp32
    const int grid = (rows + ROWS_PER_BLOCK - 1) / ROWS_PER_BLOCK;
    mlp_fused_kernel<<<grid, THREADS>>>(x, (float*)d_out, p, rows);
}